// round 2
// baseline (speedup 1.0000x reference)
#include <cuda_runtime.h>
#include <stdint.h>

// QLinearLayerSign: out[m][n] = sum_k (x[m,k]>0) * W[n,k],  W in {-1,+1}
// Binary-GEMM formulation:
//   Xb[m]  = bitmask of (x[m,:] > 0)          (128 uint32 per row)
//   Wb[n]  = bitmask of (W[n,:] > 0)  (+1 bit) (128 uint32 per row)
//   R[m]   = popcount of Xb[m] over the whole row
//   out[m][n] = 2 * sum_w popc(Xb[m][w] & Wb[n][w]) - R[m]

#define BATCH 8192
#define INF   4096
#define OUTF  4096
#define KW    (INF / 32)   // 128 words of packed K

// Scratch (no cudaMalloc allowed): 4MB + 2MB + 32KB
__device__ uint32_t g_Xb[BATCH * KW];
__device__ uint32_t g_Wb[OUTF * KW];
__device__ int      g_Xr[BATCH];

// ---------------------------------------------------------------------------
// Pack: each warp produces one 32-bit word via ballot. Rows are contiguous and
// INF is a multiple of 32, so word index gw maps to elements [gw*32, gw*32+32).
// ---------------------------------------------------------------------------
__global__ __launch_bounds__(256) void pack_bits_kernel(
    const float* __restrict__ src, uint32_t* __restrict__ dst, int total_words)
{
    int gw   = (int)((blockIdx.x * blockDim.x + threadIdx.x) >> 5);
    int lane = threadIdx.x & 31;
    if (gw >= total_words) return;
    float v = src[(size_t)gw * 32 + lane];
    unsigned mask = __ballot_sync(0xFFFFFFFFu, v > 0.0f);
    if (lane == 0) dst[gw] = mask;
}

// ---------------------------------------------------------------------------
// Per-row popcount of packed X (one warp per row).
// ---------------------------------------------------------------------------
__global__ __launch_bounds__(256) void row_popc_kernel(
    const uint32_t* __restrict__ Xb, int* __restrict__ Xr, int rows)
{
    int row  = (int)(blockIdx.x * (blockDim.x >> 5) + (threadIdx.x >> 5));
    int lane = threadIdx.x & 31;
    if (row >= rows) return;
    const uint32_t* p = Xb + (size_t)row * KW;
    int s = 0;
    #pragma unroll
    for (int i = 0; i < KW / 32; i++) s += __popc(p[lane + i * 32]);
    #pragma unroll
    for (int o = 16; o; o >>= 1) s += __shfl_xor_sync(0xFFFFFFFFu, s, o);
    if (lane == 0) Xr[row] = s;
}

// ---------------------------------------------------------------------------
// Binary GEMM: 64x64 output tile per CTA, BK=32 packed words per k-step.
// 256 threads, each computes a 4x4 register tile of popcount-dot accumulators.
// ---------------------------------------------------------------------------
#define BM 64
#define BN 64
#define BK 32

__global__ __launch_bounds__(256) void bgemm_popc_kernel(
    const uint32_t* __restrict__ Xb,
    const uint32_t* __restrict__ Wb,
    const int*      __restrict__ Xr,
    float*          __restrict__ out)
{
    // +1 padding: tile stores (stride 33 words) hit 32 distinct banks;
    // a-loads broadcast, b-loads worst-case 2-way.
    __shared__ uint32_t Xs[BM][BK + 1];
    __shared__ uint32_t Ws[BN][BK + 1];

    const int tx = threadIdx.x & 15;   // -> n direction (4 cols each)
    const int ty = threadIdx.x >> 4;   // -> m direction (4 rows each)
    const int m0 = blockIdx.y * BM;
    const int n0 = blockIdx.x * BN;

    const int lr = threadIdx.x >> 5;   // 0..7  (tile-load row group)
    const int lw = threadIdx.x & 31;   // 0..31 (tile-load word)

    int acc[4][4] = {};

    for (int k0 = 0; k0 < KW; k0 += BK) {
        // Load 64x32 words of X and W tiles (8 rows per thread-group pass).
        #pragma unroll
        for (int it = 0; it < 8; it++) {
            int r = lr + it * 8;
            Xs[r][lw] = Xb[(size_t)(m0 + r) * KW + k0 + lw];
            Ws[r][lw] = Wb[(size_t)(n0 + r) * KW + k0 + lw];
        }
        __syncthreads();

        #pragma unroll 4
        for (int kk = 0; kk < BK; kk++) {
            uint32_t a0 = Xs[ty * 4 + 0][kk];
            uint32_t a1 = Xs[ty * 4 + 1][kk];
            uint32_t a2 = Xs[ty * 4 + 2][kk];
            uint32_t a3 = Xs[ty * 4 + 3][kk];
            uint32_t b0 = Ws[tx * 4 + 0][kk];
            uint32_t b1 = Ws[tx * 4 + 1][kk];
            uint32_t b2 = Ws[tx * 4 + 2][kk];
            uint32_t b3 = Ws[tx * 4 + 3][kk];

            acc[0][0] += __popc(a0 & b0); acc[0][1] += __popc(a0 & b1);
            acc[0][2] += __popc(a0 & b2); acc[0][3] += __popc(a0 & b3);
            acc[1][0] += __popc(a1 & b0); acc[1][1] += __popc(a1 & b1);
            acc[1][2] += __popc(a1 & b2); acc[1][3] += __popc(a1 & b3);
            acc[2][0] += __popc(a2 & b0); acc[2][1] += __popc(a2 & b1);
            acc[2][2] += __popc(a2 & b2); acc[2][3] += __popc(a2 & b3);
            acc[3][0] += __popc(a3 & b0); acc[3][1] += __popc(a3 & b1);
            acc[3][2] += __popc(a3 & b2); acc[3][3] += __popc(a3 & b3);
        }
        __syncthreads();
    }

    // Epilogue: out = 2*S - R[m], vectorized float4 stores.
    #pragma unroll
    for (int i = 0; i < 4; i++) {
        int m = m0 + ty * 4 + i;
        int R = Xr[m];
        float4 v;
        v.x = (float)(2 * acc[i][0] - R);
        v.y = (float)(2 * acc[i][1] - R);
        v.z = (float)(2 * acc[i][2] - R);
        v.w = (float)(2 * acc[i][3] - R);
        *reinterpret_cast<float4*>(&out[(size_t)m * OUTF + n0 + tx * 4]) = v;
    }
}

// ---------------------------------------------------------------------------
extern "C" void kernel_launch(void* const* d_in, const int* in_sizes, int n_in,
                              void* d_out, int out_size)
{
    // metadata order: x [8192*4096], W [4096*4096]; verify by element count.
    const float* x = (const float*)d_in[0];
    const float* W = (const float*)d_in[1];
    if (n_in >= 2 && in_sizes[0] == OUTF * INF && in_sizes[1] == BATCH * INF) {
        // swapped order (defensive)
        x = (const float*)d_in[1];
        W = (const float*)d_in[0];
    }
    float* out = (float*)d_out;

    uint32_t* Xb; uint32_t* Wb; int* Xr;
    cudaGetSymbolAddress((void**)&Xb, g_Xb);
    cudaGetSymbolAddress((void**)&Wb, g_Wb);
    cudaGetSymbolAddress((void**)&Xr, g_Xr);

    // Pack x: BATCH*KW words, one warp per word.
    {
        int words = BATCH * KW;                 // 1,048,576
        int threads = 256;
        int blocks = (words * 32 + threads - 1) / threads;
        pack_bits_kernel<<<blocks, threads>>>(x, Xb, words);
    }
    // Pack W.
    {
        int words = OUTF * KW;                  // 524,288
        int threads = 256;
        int blocks = (words * 32 + threads - 1) / threads;
        pack_bits_kernel<<<blocks, threads>>>(W, Wb, words);
    }
    // Row popcounts of X.
    {
        int threads = 256;                      // 8 warps -> 8 rows per block
        int blocks = (BATCH + 7) / 8;
        row_popc_kernel<<<blocks, threads>>>(Xb, Xr, BATCH);
    }
    // Binary GEMM.
    {
        dim3 grid(OUTF / BN, BATCH / BM);       // (64, 128)
        bgemm_popc_kernel<<<grid, 256>>>(Xb, Wb, Xr, out);
    }
}